// round 4
// baseline (speedup 1.0000x reference)
#include <cuda_runtime.h>
#include <math.h>

#define NDAG  16384
#define NNODE 48
#define D     62
#define DP    64
#define NCLS  500
#define DPC   2     // dags per CTA in scan kernel
#define NPOOL 256   // pool partial blocks

// -------- scratch (static device globals; no runtime allocation) ----------
__device__ float g_atomP[(size_t)NDAG * NNODE * D];  // W_merge[:,62:]@atom + b_merge
__device__ float g_last[(size_t)NDAG * D];           // sink outputs per DAG
__device__ float g_logit[NDAG];                      // last . dag_w
__device__ int   g_maxbits;                          // order-encoded max logit
__device__ float g_part[NPOOL * 64];                 // [c][0..61]=numerator, [62]=sumE

__device__ __forceinline__ int enc_f(float f) {
    int i = __float_as_int(f);
    return (i >= 0) ? i : (i ^ 0x7FFFFFFF);
}

// ============================================================================
// K1: atomP[node,g] = b_merge[g] + sum_k W_merge[g][62+k] * atoms[node,k]
// Fully coalesced: atoms staged into smem (pitch 63, conflict-free per-thread
// row reads), output staged back through the same buffer, stored coalesced.
// ============================================================================
__global__ void __launch_bounds__(128) k_atomP(const float* __restrict__ atoms,
                                               const float* __restrict__ W_merge,
                                               const float* __restrict__ b_merge) {
    __shared__ float As[128 * 63];   // 128 node-rows, pitch 63
    __shared__ float Ws[D][DP];      // Ws[g][k] = W_merge[g][62+k], zero-padded
    __shared__ float bs[DP];
    int tid = threadIdx.x;
    if (blockIdx.x == 0 && tid == 0) g_maxbits = 0x80000000;  // INT_MIN, every launch

    for (int i = tid; i < D * DP; i += 128) {
        int gg = i >> 6, k = i & 63;
        Ws[gg][k] = (k < D) ? W_merge[gg * (2 * D) + D + k] : 0.f;
    }
    if (tid < DP) bs[tid] = (tid < D) ? b_merge[tid] : 0.f;

    size_t base = (size_t)blockIdx.x * 128 * D;
    // coalesced load, scatter to pitch-63 rows
#pragma unroll 1
    for (int j = 0; j < D; j++) {
        unsigned idx = j * 128u + tid;
        unsigned row = idx / D, col = idx - row * D;
        As[row * 63 + col] = atoms[base + idx];
    }
    __syncthreads();

    float a[DP];
#pragma unroll
    for (int k = 0; k < D; k++) a[k] = As[tid * 63 + k];
    a[62] = 0.f; a[63] = 0.f;
    __syncthreads();   // all rows consumed before As is reused as output staging

#pragma unroll 2
    for (int gg = 0; gg < D; gg++) {
        float acc = bs[gg];
#pragma unroll
        for (int k = 0; k < DP; k += 4) {
            float4 w = *(const float4*)&Ws[gg][k];   // warp-uniform -> broadcast
            acc += a[k] * w.x + a[k + 1] * w.y + a[k + 2] * w.z + a[k + 3] * w.w;
        }
        As[tid * 63 + gg] = acc;
    }
    __syncthreads();

    // coalesced store
#pragma unroll 1
    for (int j = 0; j < D; j++) {
        unsigned idx = j * 128u + tid;
        unsigned row = idx / D, col = idx - row * D;
        g_atomP[base + idx] = As[row * 63 + col];
    }
}

// ============================================================================
// K2: sequential DAG scan. 2 DAGs/CTA, 64 threads/DAG (thread = out dim).
// z[t] = W_agg @ out[t], sdot[t] = out[t].att_w stored instead of raw outs.
// atomP prefetched one step ahead; preds preloaded to smem; logit fused.
// ============================================================================
__global__ void __launch_bounds__(128, 5) k_scan(const float* __restrict__ atoms,
                                                 const int*   __restrict__ preds,
                                                 const float* __restrict__ W_single,
                                                 const float* __restrict__ b_single,
                                                 const float* __restrict__ W_merge,
                                                 const float* __restrict__ att_w,
                                                 const float* __restrict__ dag_w) {
    __shared__ float z_sh[DPC][NNODE][DP];
    __shared__ float out_sh[DPC][DP];
    __shared__ float sdot_sh[DPC][NNODE];
    __shared__ int4  pred_sh[DPC][NNODE];
    __shared__ float attw[DP], bsg[DP];
    __shared__ float red_sh[4];

    int tid = threadIdx.x;
    int dl  = tid >> 6;                // local dag (warp-uniform)
    int g   = tid & 63;                // output dim
    long d  = (long)blockIdx.x * DPC + dl;

    // preds for this CTA's 2 DAGs, coalesced
    {
        const int* src = preds + (long)blockIdx.x * DPC * NNODE * 4;
        int* dst = (int*)pred_sh;
        for (int i = tid; i < DPC * NNODE * 4; i += 128) dst[i] = src[i];
    }
    if (tid < DP) {
        attw[tid] = (tid < D) ? att_w[tid] : 0.f;
        bsg[tid]  = (tid < D) ? b_single[tid] : 0.f;
    }
    // W_agg row (first 62 cols of W_merge) in registers
    float Wr[DP];
#pragma unroll
    for (int k = 0; k < D; k++) Wr[k] = (g < D) ? W_merge[g * (2 * D) + k] : 0.f;
    Wr[62] = 0.f; Wr[63] = 0.f;
    float dagw = (g < D) ? dag_w[g] : 0.f;
    __syncthreads();

    float mp_next = (g < D) ? g_atomP[(d * NNODE) * D + g] : 0.f;

#pragma unroll 1
    for (int t = 0; t < NNODE; t++) {
        float mp = mp_next;
        if (t + 1 < NNODE && g < D)
            mp_next = g_atomP[(d * NNODE + t + 1) * D + g];   // prefetch next step

        int4 pv = pred_sh[dl][t];
        float outv;
        bool has = (pv.x >= 0) | (pv.y >= 0) | (pv.z >= 0) | (pv.w >= 0);
        if (has) {
            float s0 = (pv.x >= 0) ? sdot_sh[dl][pv.x] : -3.0e38f;
            float s1 = (pv.y >= 0) ? sdot_sh[dl][pv.y] : -3.0e38f;
            float s2 = (pv.z >= 0) ? sdot_sh[dl][pv.z] : -3.0e38f;
            float s3 = (pv.w >= 0) ? sdot_sh[dl][pv.w] : -3.0e38f;
            float m = fmaxf(fmaxf(s0, s1), fmaxf(s2, s3));
            float e0 = (pv.x >= 0) ? expf(s0 - m) : 0.f;
            float e1 = (pv.y >= 0) ? expf(s1 - m) : 0.f;
            float e2 = (pv.z >= 0) ? expf(s2 - m) : 0.f;
            float e3 = (pv.w >= 0) ? expf(s3 - m) : 0.f;
            float sum = e0 + e1 + e2 + e3;
            int p0 = pv.x < 0 ? 0 : pv.x;
            int p1 = pv.y < 0 ? 0 : pv.y;
            int p2 = pv.z < 0 ? 0 : pv.z;
            int p3 = pv.w < 0 ? 0 : pv.w;
            float za = e0 * z_sh[dl][p0][g] + e1 * z_sh[dl][p1][g]
                     + e2 * z_sh[dl][p2][g] + e3 * z_sh[dl][p3][g];
            outv = fmaxf(mp + za / sum, 0.f);
        } else if (g < D) {
            // rare (t=0 always; t>0 with p~0.0016): relu(W_single@atom + b)
            const float* arow = atoms + (d * NNODE + t) * D;   // uniform, bcast
            const float* wrow = W_single + g * D;               // L2-hot
            float acc = bsg[g];
#pragma unroll
            for (int k = 0; k < 31; k++) {
                float2 av = *(const float2*)(arow + 2 * k);
                float2 wv = *(const float2*)(wrow + 2 * k);
                acc += wv.x * av.x + wv.y * av.y;
            }
            outv = fmaxf(acc, 0.f);
        } else {
            outv = 0.f;
        }
        out_sh[dl][g] = (g < D) ? outv : 0.f;
        __syncthreads();

        if (g < D) {
            float z0 = 0.f, z1 = 0.f, z2 = 0.f, z3 = 0.f;
#pragma unroll
            for (int k = 0; k < DP; k += 4) {
                float4 o = *(const float4*)&out_sh[dl][k];   // broadcast
                z0 += Wr[k]     * o.x;  z1 += Wr[k + 1] * o.y;
                z2 += Wr[k + 2] * o.z;  z3 += Wr[k + 3] * o.w;
            }
            z_sh[dl][t][g] = (z0 + z1) + (z2 + z3);
            if (t == NNODE - 1) g_last[d * D + g] = outv;
        } else if (g == D) {
            float s0 = 0.f, s1 = 0.f, s2 = 0.f, s3 = 0.f;
#pragma unroll
            for (int k = 0; k < DP; k += 4) {
                s0 += out_sh[dl][k]     * attw[k];
                s1 += out_sh[dl][k + 1] * attw[k + 1];
                s2 += out_sh[dl][k + 2] * attw[k + 2];
                s3 += out_sh[dl][k + 3] * attw[k + 3];
            }
            sdot_sh[dl][t] = (s0 + s1) + (s2 + s3);
        }
        __syncthreads();
    }

    // fused logit: L[d] = out_47 . dag_w  (out_sh holds final outputs)
    float lg = out_sh[dl][g] * dagw;
#pragma unroll
    for (int o = 16; o > 0; o >>= 1) lg += __shfl_xor_sync(0xffffffffu, lg, o);
    if ((tid & 31) == 0) red_sh[tid >> 5] = lg;
    __syncthreads();
    if (g == 0) {
        float L = red_sh[dl * 2] + red_sh[dl * 2 + 1];
        g_logit[d] = L;
        atomicMax(&g_maxbits, enc_f(L));
    }
}

// ============================================================================
// K3: partial softmax-pool. 256 blocks x 64 threads, 64 DAGs per block.
// ============================================================================
__global__ void __launch_bounds__(64) k_pool() {
    __shared__ float e_sh[64];
    int tid = threadIdx.x;
    long base = (long)blockIdx.x * 64;
    int mb = g_maxbits;
    float M = __int_as_float(mb >= 0 ? mb : (mb ^ 0x7FFFFFFF));
    e_sh[tid] = expf(g_logit[base + tid] - M);
    __syncthreads();
    if (tid < D) {
        float pool = 0.f;
#pragma unroll 4
        for (int i = 0; i < 64; i++)
            pool += e_sh[i] * g_last[(base + i) * D + tid];
        g_part[blockIdx.x * 64 + tid] = pool;
    } else if (tid == D) {
        float sE = 0.f;
#pragma unroll
        for (int i = 0; i < 64; i++) sE += e_sh[i];
        g_part[blockIdx.x * 64 + D] = sE;
    }
}

// ============================================================================
// K4: reduce partials -> pooled; out = sigmoid(W_final @ pooled + b_final)
// ============================================================================
__global__ void __launch_bounds__(512) k_final(const float* __restrict__ W_final,
                                               const float* __restrict__ b_final,
                                               float* __restrict__ out) {
    __shared__ float pooled[64];
    int tid = threadIdx.x;
    if (tid <= D) {
        float s = 0.f;
        for (int c = 0; c < NPOOL; c++) s += g_part[c * 64 + tid];
        pooled[tid] = s;            // pooled[62] = sumE
    }
    __syncthreads();
    float inv = 1.f / pooled[D];
    if (tid < NCLS) {
        float acc = 0.f;
#pragma unroll
        for (int k = 0; k < D; k++) acc += W_final[tid * D + k] * pooled[k];
        acc = b_final[tid] + acc * inv;
        out[tid] = 1.f / (1.f + expf(-acc));
    }
}

// ============================================================================
extern "C" void kernel_launch(void* const* d_in, const int* in_sizes, int n_in,
                              void* d_out, int out_size) {
    const float* atoms    = (const float*)d_in[0];
    const int*   preds    = (const int*)  d_in[1];
    const float* W_single = (const float*)d_in[2];
    const float* b_single = (const float*)d_in[3];
    const float* W_merge  = (const float*)d_in[4];
    const float* b_merge  = (const float*)d_in[5];
    const float* att_w    = (const float*)d_in[6];
    const float* dag_w    = (const float*)d_in[7];
    const float* W_final  = (const float*)d_in[8];
    const float* b_final  = (const float*)d_in[9];
    float* out = (float*)d_out;

    k_atomP<<<NDAG * NNODE / 128, 128>>>(atoms, W_merge, b_merge);
    k_scan<<<NDAG / DPC, 128>>>(atoms, preds, W_single, b_single, W_merge, att_w, dag_w);
    k_pool<<<NPOOL, 64>>>();
    k_final<<<1, 512>>>(W_final, b_final, out);
}

// round 5
// speedup vs baseline: 1.0981x; 1.0981x over previous
#include <cuda_runtime.h>
#include <math.h>

#define NDAG  16384
#define NNODE 48
#define D     62
#define DP    64
#define NCLS  500
#define DPC   2     // dags per CTA in scan kernel
#define NPOOL 256   // pool partial blocks

typedef unsigned long long ull;

// -------- scratch (static device globals; no runtime allocation) ----------
__device__ float g_atomP[(size_t)NDAG * NNODE * D];  // W_merge[:,62:]@atom + b_merge
__device__ float g_last[(size_t)NDAG * D];           // sink outputs per DAG
__device__ float g_logit[NDAG];                      // last . dag_w
__device__ int   g_maxbits;                          // order-encoded max logit
__device__ float g_part[NPOOL * 64];                 // [c][0..61]=numerator, [62]=sumE

__device__ __forceinline__ int enc_f(float f) {
    int i = __float_as_int(f);
    return (i >= 0) ? i : (i ^ 0x7FFFFFFF);
}
// packed fp32x2 FMA (Blackwell FFMA2 — only reachable via PTX)
__device__ __forceinline__ void ffma2(ull& d, ull a, ull b) {
    asm("fma.rn.f32x2 %0, %1, %2, %0;" : "+l"(d) : "l"(a), "l"(b));
}
__device__ __forceinline__ ull pack2(float lo, float hi) {
    ull r;
    asm("mov.b64 %0, {%1, %2};" : "=l"(r)
        : "r"(__float_as_uint(lo)), "r"(__float_as_uint(hi)));
    return r;
}
__device__ __forceinline__ float2 unpack2(ull v) {
    unsigned lo, hi;
    asm("mov.b64 {%0, %1}, %2;" : "=r"(lo), "=r"(hi) : "l"(v));
    return make_float2(__uint_as_float(lo), __uint_as_float(hi));
}
__device__ __forceinline__ void dag_bar(int dl) {
    asm volatile("bar.sync %0, %1;" :: "r"(dl + 1), "r"(64) : "memory");
}

// ============================================================================
// K1: atomP[node,g] = b_merge[g] + sum_k W_merge[g][62+k] * atoms[node,k]
// Coalesced global I/O via pitch-63 smem staging; inner loop in fp32x2.
// ============================================================================
__global__ void __launch_bounds__(128) k_atomP(const float* __restrict__ atoms,
                                               const float* __restrict__ W_merge,
                                               const float* __restrict__ b_merge) {
    __shared__ __align__(16) float As[128 * 63];   // 128 node-rows, pitch 63
    __shared__ __align__(16) float Ws[D][DP];      // Ws[g][k] = W_merge[g][62+k]
    __shared__ float bs[DP];
    int tid = threadIdx.x;
    if (blockIdx.x == 0 && tid == 0) g_maxbits = 0x80000000;  // reset every launch

    for (int i = tid; i < D * DP; i += 128) {
        int gg = i >> 6, k = i & 63;
        Ws[gg][k] = (k < D) ? W_merge[gg * (2 * D) + D + k] : 0.f;
    }
    if (tid < DP) bs[tid] = (tid < D) ? b_merge[tid] : 0.f;

    size_t base = (size_t)blockIdx.x * 128 * D;
#pragma unroll 1
    for (int j = 0; j < D; j++) {                  // coalesced load -> pitch-63
        unsigned idx = j * 128u + tid;
        unsigned row = idx / D, col = idx - row * D;
        As[row * 63 + col] = atoms[base + idx];
    }
    __syncthreads();

    ull a2[32];                                    // atom row packed f32x2
#pragma unroll
    for (int k = 0; k < 31; k++)
        a2[k] = pack2(As[tid * 63 + 2 * k], As[tid * 63 + 2 * k + 1]);
    a2[31] = 0ULL;
    __syncthreads();                               // As reused as output staging

#pragma unroll 2
    for (int gg = 0; gg < D; gg++) {
        ull acc0 = pack2(bs[gg], 0.f), acc1 = 0ULL;
#pragma unroll
        for (int k2 = 0; k2 < 32; k2 += 2) {
            ulonglong2 w = *(const ulonglong2*)&Ws[gg][2 * k2];  // uniform bcast
            ffma2(acc0, a2[k2],     w.x);
            ffma2(acc1, a2[k2 + 1], w.y);
        }
        float2 f0 = unpack2(acc0), f1 = unpack2(acc1);
        As[tid * 63 + gg] = (f0.x + f0.y) + (f1.x + f1.y);
    }
    __syncthreads();

#pragma unroll 1
    for (int j = 0; j < D; j++) {                  // coalesced store
        unsigned idx = j * 128u + tid;
        unsigned row = idx / D, col = idx - row * D;
        g_atomP[base + idx] = As[row * 63 + col];
    }
}

// ============================================================================
// K2: sequential DAG scan. 2 DAGs/CTA, 64 threads/DAG (thread = out dim).
// z[t] = W_agg @ out[t] (fp32x2 inner loop), sdot[t] = out[t].att_w.
// Per-DAG named barriers; atomP prefetch; fused logit + atomicMax.
// ============================================================================
__global__ void __launch_bounds__(128) k_scan(const float* __restrict__ atoms,
                                              const int*   __restrict__ preds,
                                              const float* __restrict__ W_single,
                                              const float* __restrict__ b_single,
                                              const float* __restrict__ W_merge,
                                              const float* __restrict__ att_w,
                                              const float* __restrict__ dag_w) {
    __shared__ float z_sh[DPC][NNODE][DP];
    __shared__ __align__(16) float out_sh[DPC][DP];
    __shared__ float sdot_sh[DPC][NNODE];
    __shared__ int4  pred_sh[DPC][NNODE];
    __shared__ __align__(16) ull attw2[32];
    __shared__ float bsg[DP];
    __shared__ float red_sh[4];

    int tid = threadIdx.x;
    int dl  = tid >> 6;                // local dag (warp-uniform)
    int g   = tid & 63;                // output dim
    long d  = (long)blockIdx.x * DPC + dl;

    {   // preds for this CTA's 2 DAGs, coalesced
        const int* src = preds + (long)blockIdx.x * DPC * NNODE * 4;
        int* dst = (int*)pred_sh;
        for (int i = tid; i < DPC * NNODE * 4; i += 128) dst[i] = src[i];
    }
    if (tid < 32) {
        float lo = (2 * tid     < D) ? att_w[2 * tid]     : 0.f;
        float hi = (2 * tid + 1 < D) ? att_w[2 * tid + 1] : 0.f;
        attw2[tid] = pack2(lo, hi);
    }
    if (tid < DP) bsg[tid] = (tid < D) ? b_single[tid] : 0.f;

    // W_agg row (first 62 cols of W_merge), packed f32x2 in registers
    ull Wr2[32];
#pragma unroll
    for (int k = 0; k < 31; k++) {
        float lo = (g < D) ? W_merge[g * (2 * D) + 2 * k]     : 0.f;
        float hi = (g < D) ? W_merge[g * (2 * D) + 2 * k + 1] : 0.f;
        Wr2[k] = pack2(lo, hi);
    }
    Wr2[31] = 0ULL;
    float dagw = (g < D) ? dag_w[g] : 0.f;
    __syncthreads();

    float mp_next = (g < D) ? g_atomP[(d * NNODE) * D + g] : 0.f;

#pragma unroll 1
    for (int t = 0; t < NNODE; t++) {
        float mp = mp_next;
        if (t + 1 < NNODE && g < D)
            mp_next = g_atomP[(d * NNODE + t + 1) * D + g];   // prefetch

        int4 pv = pred_sh[dl][t];
        float outv;
        bool has = (pv.x >= 0) | (pv.y >= 0) | (pv.z >= 0) | (pv.w >= 0);
        if (has) {
            float s0 = (pv.x >= 0) ? sdot_sh[dl][pv.x] : -3.0e38f;
            float s1 = (pv.y >= 0) ? sdot_sh[dl][pv.y] : -3.0e38f;
            float s2 = (pv.z >= 0) ? sdot_sh[dl][pv.z] : -3.0e38f;
            float s3 = (pv.w >= 0) ? sdot_sh[dl][pv.w] : -3.0e38f;
            float m = fmaxf(fmaxf(s0, s1), fmaxf(s2, s3));
            float e0 = (pv.x >= 0) ? expf(s0 - m) : 0.f;
            float e1 = (pv.y >= 0) ? expf(s1 - m) : 0.f;
            float e2 = (pv.z >= 0) ? expf(s2 - m) : 0.f;
            float e3 = (pv.w >= 0) ? expf(s3 - m) : 0.f;
            float sum = e0 + e1 + e2 + e3;
            int p0 = pv.x < 0 ? 0 : pv.x;
            int p1 = pv.y < 0 ? 0 : pv.y;
            int p2 = pv.z < 0 ? 0 : pv.z;
            int p3 = pv.w < 0 ? 0 : pv.w;
            float za = e0 * z_sh[dl][p0][g] + e1 * z_sh[dl][p1][g]
                     + e2 * z_sh[dl][p2][g] + e3 * z_sh[dl][p3][g];
            outv = fmaxf(mp + za / sum, 0.f);
        } else if (g < D) {
            // rare (t=0 always; t>0 with p~0.0016): relu(W_single@atom + b)
            const float* arow = atoms + (d * NNODE + t) * D;   // uniform, bcast
            const float* wrow = W_single + g * D;               // L2-hot
            float acc = bsg[g];
#pragma unroll
            for (int k = 0; k < 31; k++) {
                float2 av = *(const float2*)(arow + 2 * k);
                float2 wv = *(const float2*)(wrow + 2 * k);
                acc += wv.x * av.x + wv.y * av.y;
            }
            outv = fmaxf(acc, 0.f);
        } else {
            outv = 0.f;
        }
        out_sh[dl][g] = (g < D) ? outv : 0.f;
        dag_bar(dl);

        if (g < D) {
            ull acc0 = 0ULL, acc1 = 0ULL;
#pragma unroll
            for (int k2 = 0; k2 < 32; k2 += 2) {
                ulonglong2 o = *(const ulonglong2*)&out_sh[dl][2 * k2];  // bcast
                ffma2(acc0, Wr2[k2],     o.x);
                ffma2(acc1, Wr2[k2 + 1], o.y);
            }
            float2 f0 = unpack2(acc0), f1 = unpack2(acc1);
            z_sh[dl][t][g] = (f0.x + f0.y) + (f1.x + f1.y);
            if (t == NNODE - 1) g_last[d * D + g] = outv;
        } else if (g == D) {
            ull s0 = 0ULL, s1 = 0ULL;
#pragma unroll
            for (int k2 = 0; k2 < 32; k2 += 2) {
                ulonglong2 o = *(const ulonglong2*)&out_sh[dl][2 * k2];
                ffma2(s0, attw2[k2],     o.x);
                ffma2(s1, attw2[k2 + 1], o.y);
            }
            float2 f0 = unpack2(s0), f1 = unpack2(s1);
            sdot_sh[dl][t] = (f0.x + f0.y) + (f1.x + f1.y);
        }
        dag_bar(dl);
    }

    // fused logit: L[d] = out_47 . dag_w
    float lg = out_sh[dl][g] * dagw;
#pragma unroll
    for (int o = 16; o > 0; o >>= 1) lg += __shfl_xor_sync(0xffffffffu, lg, o);
    if ((tid & 31) == 0) red_sh[tid >> 5] = lg;
    dag_bar(dl);
    if (g == 0) {
        float L = red_sh[dl * 2] + red_sh[dl * 2 + 1];
        g_logit[d] = L;
        atomicMax(&g_maxbits, enc_f(L));
    }
}

// ============================================================================
// K3: partial softmax-pool. 256 blocks x 64 threads, 64 DAGs per block.
// ============================================================================
__global__ void __launch_bounds__(64) k_pool() {
    __shared__ float e_sh[64];
    int tid = threadIdx.x;
    long base = (long)blockIdx.x * 64;
    int mb = g_maxbits;
    float M = __int_as_float(mb >= 0 ? mb : (mb ^ 0x7FFFFFFF));
    e_sh[tid] = expf(g_logit[base + tid] - M);
    __syncthreads();
    if (tid < D) {
        float pool = 0.f;
#pragma unroll 4
        for (int i = 0; i < 64; i++)
            pool += e_sh[i] * g_last[(base + i) * D + tid];
        g_part[blockIdx.x * 64 + tid] = pool;
    } else if (tid == D) {
        float sE = 0.f;
#pragma unroll
        for (int i = 0; i < 64; i++) sE += e_sh[i];
        g_part[blockIdx.x * 64 + D] = sE;
    }
}

// ============================================================================
// K4: reduce partials -> pooled; out = sigmoid(W_final @ pooled + b_final)
// ============================================================================
__global__ void __launch_bounds__(512) k_final(const float* __restrict__ W_final,
                                               const float* __restrict__ b_final,
                                               float* __restrict__ out) {
    __shared__ float part[8][64];
    __shared__ float pooled[64];
    int tid = threadIdx.x;
    int c = tid >> 6, col = tid & 63;
    float s = 0.f;
    for (int b = c; b < NPOOL; b += 8) s += g_part[b * 64 + col];
    part[c][col] = s;
    __syncthreads();
    if (tid < 64) {
        float t = 0.f;
#pragma unroll
        for (int i = 0; i < 8; i++) t += part[i][tid];
        pooled[tid] = t;            // pooled[62] = sumE
    }
    __syncthreads();
    float inv = 1.f / pooled[D];
    if (tid < NCLS) {
        float acc = 0.f;
#pragma unroll
        for (int k = 0; k < D; k++) acc += W_final[tid * D + k] * pooled[k];
        acc = b_final[tid] + acc * inv;
        out[tid] = 1.f / (1.f + expf(-acc));
    }
}

// ============================================================================
extern "C" void kernel_launch(void* const* d_in, const int* in_sizes, int n_in,
                              void* d_out, int out_size) {
    const float* atoms    = (const float*)d_in[0];
    const int*   preds    = (const int*)  d_in[1];
    const float* W_single = (const float*)d_in[2];
    const float* b_single = (const float*)d_in[3];
    const float* W_merge  = (const float*)d_in[4];
    const float* b_merge  = (const float*)d_in[5];
    const float* att_w    = (const float*)d_in[6];
    const float* dag_w    = (const float*)d_in[7];
    const float* W_final  = (const float*)d_in[8];
    const float* b_final  = (const float*)d_in[9];
    float* out = (float*)d_out;

    k_atomP<<<NDAG * NNODE / 128, 128>>>(atoms, W_merge, b_merge);
    k_scan<<<NDAG / DPC, 128>>>(atoms, preds, W_single, b_single, W_merge, att_w, dag_w);
    k_pool<<<NPOOL, 64>>>();
    k_final<<<1, 512>>>(W_final, b_final, out);
}

// round 7
// speedup vs baseline: 1.1178x; 1.0179x over previous
#include <cuda_runtime.h>
#include <math.h>

#define NDAG  16384
#define NNODE 48
#define D     62
#define DP    64
#define NCLS  500
#define DPC   2     // dags per CTA in scan kernel
#define NPOOL 256   // pool partial blocks

typedef unsigned long long ull;

// -------- scratch (static device globals; no runtime allocation) ----------
__device__ float g_atomP[(size_t)NDAG * NNODE * D];  // W_merge[:,62:]@atom + b_merge
__device__ float g_last[(size_t)NDAG * D];           // sink outputs per DAG
__device__ float g_logit[NDAG];                      // last . dag_w
__device__ int   g_maxbits;                          // order-encoded max logit
__device__ float g_part[NPOOL * 64];                 // [c][0..61]=numerator, [62]=sumE

__device__ __forceinline__ int enc_f(float f) {
    int i = __float_as_int(f);
    return (i >= 0) ? i : (i ^ 0x7FFFFFFF);
}
// packed fp32x2 FMA (Blackwell FFMA2 — only reachable via PTX)
__device__ __forceinline__ void ffma2(ull& d, ull a, ull b) {
    asm("fma.rn.f32x2 %0, %1, %2, %0;" : "+l"(d) : "l"(a), "l"(b));
}
__device__ __forceinline__ ull pack2(float lo, float hi) {
    ull r;
    asm("mov.b64 %0, {%1, %2};" : "=l"(r)
        : "r"(__float_as_uint(lo)), "r"(__float_as_uint(hi)));
    return r;
}
__device__ __forceinline__ float2 unpack2(ull v) {
    unsigned lo, hi;
    asm("mov.b64 {%0, %1}, %2;" : "=r"(lo), "=r"(hi) : "l"(v));
    return make_float2(__uint_as_float(lo), __uint_as_float(hi));
}
__device__ __forceinline__ void dag_bar(int dl) {
    asm volatile("bar.sync %0, %1;" :: "r"(dl + 1), "r"(64) : "memory");
}

// ============================================================================
// K0a/K0b: padding no-ops so the ncu capture window (4th launch) lands on
// k_scan. K0b also resets the global max.
// ============================================================================
__global__ void k_nop() {}
__global__ void k_reset() { if (threadIdx.x == 0) g_maxbits = 0x80000000; }

// ============================================================================
// K1: atomP[node,g] = b_merge[g] + sum_k W_merge[g][62+k] * atoms[node,k]
// Coalesced global I/O via pitch-63 smem staging; inner loop in fp32x2.
// ============================================================================
__global__ void __launch_bounds__(128) k_atomP(const float* __restrict__ atoms,
                                               const float* __restrict__ W_merge,
                                               const float* __restrict__ b_merge) {
    __shared__ __align__(16) float As[128 * 63];   // 128 node-rows, pitch 63
    __shared__ __align__(16) float Ws[D][DP];      // Ws[g][k] = W_merge[g][62+k]
    __shared__ float bs[DP];
    int tid = threadIdx.x;

    for (int i = tid; i < D * DP; i += 128) {
        int gg = i >> 6, k = i & 63;
        Ws[gg][k] = (k < D) ? W_merge[gg * (2 * D) + D + k] : 0.f;
    }
    if (tid < DP) bs[tid] = (tid < D) ? b_merge[tid] : 0.f;

    size_t base = (size_t)blockIdx.x * 128 * D;
    {   // coalesced load -> pitch-63 rows (incremental row/col: 128 = 2*62+4)
        unsigned row = (unsigned)tid / D, col = (unsigned)tid - row * D;
        unsigned idx = tid;
#pragma unroll 1
        for (int j = 0; j < D; j++) {
            As[row * 63 + col] = atoms[base + idx];
            idx += 128; row += 2; col += 4;
            if (col >= D) { col -= D; row++; }
        }
    }
    __syncthreads();

    ull a2[32];                                    // atom row packed f32x2
#pragma unroll
    for (int k = 0; k < 31; k++)
        a2[k] = pack2(As[tid * 63 + 2 * k], As[tid * 63 + 2 * k + 1]);
    a2[31] = 0ULL;
    __syncthreads();                               // As reused as output staging

#pragma unroll 2
    for (int gg = 0; gg < D; gg++) {
        ull acc0 = pack2(bs[gg], 0.f), acc1 = 0ULL;
#pragma unroll
        for (int k2 = 0; k2 < 32; k2 += 2) {
            ulonglong2 w = *(const ulonglong2*)&Ws[gg][2 * k2];  // uniform bcast
            ffma2(acc0, a2[k2],     w.x);
            ffma2(acc1, a2[k2 + 1], w.y);
        }
        float2 f0 = unpack2(acc0), f1 = unpack2(acc1);
        As[tid * 63 + gg] = (f0.x + f0.y) + (f1.x + f1.y);
    }
    __syncthreads();

    {   // coalesced store
        unsigned row = (unsigned)tid / D, col = (unsigned)tid - row * D;
        unsigned idx = tid;
#pragma unroll 1
        for (int j = 0; j < D; j++) {
            g_atomP[base + idx] = As[row * 63 + col];
            idx += 128; row += 2; col += 4;
            if (col >= D) { col -= D; row++; }
        }
    }
}

// ============================================================================
// K2: sequential DAG scan. 2 DAGs/CTA, 64 threads/DAG (thread = out dim).
// z[t] = W_agg @ out[t] (fp32x2), sdot[t] = out[t].att_w. Fast-math softmax.
// ============================================================================
__global__ void __launch_bounds__(128) k_scan(const float* __restrict__ atoms,
                                              const int*   __restrict__ preds,
                                              const float* __restrict__ W_single,
                                              const float* __restrict__ b_single,
                                              const float* __restrict__ W_merge,
                                              const float* __restrict__ att_w,
                                              const float* __restrict__ dag_w) {
    __shared__ float z_sh[DPC][NNODE][DP];
    __shared__ __align__(16) float out_sh[DPC][DP];
    __shared__ float sdot_sh[DPC][NNODE];
    __shared__ int4  pred_sh[DPC][NNODE];
    __shared__ __align__(16) ull attw2[32];
    __shared__ float bsg[DP];
    __shared__ float red_sh[4];

    int tid = threadIdx.x;
    int dl  = tid >> 6;                // local dag (warp-uniform)
    int g   = tid & 63;                // output dim
    long d  = (long)blockIdx.x * DPC + dl;

    {   // preds for this CTA's 2 DAGs, coalesced
        const int* src = preds + (long)blockIdx.x * DPC * NNODE * 4;
        int* dst = (int*)pred_sh;
        for (int i = tid; i < DPC * NNODE * 4; i += 128) dst[i] = src[i];
    }
    if (tid < 32) {
        float lo = (2 * tid     < D) ? att_w[2 * tid]     : 0.f;
        float hi = (2 * tid + 1 < D) ? att_w[2 * tid + 1] : 0.f;
        attw2[tid] = pack2(lo, hi);
    }
    if (tid < DP) bsg[tid] = (tid < D) ? b_single[tid] : 0.f;

    // W_agg row (first 62 cols of W_merge), packed f32x2 in registers
    ull Wr2[32];
#pragma unroll
    for (int k = 0; k < 31; k++) {
        float lo = (g < D) ? W_merge[g * (2 * D) + 2 * k]     : 0.f;
        float hi = (g < D) ? W_merge[g * (2 * D) + 2 * k + 1] : 0.f;
        Wr2[k] = pack2(lo, hi);
    }
    Wr2[31] = 0ULL;
    float dagw = (g < D) ? dag_w[g] : 0.f;
    __syncthreads();

    float mp_next = (g < D) ? g_atomP[(d * NNODE) * D + g] : 0.f;

#pragma unroll 1
    for (int t = 0; t < NNODE; t++) {
        float mp = mp_next;
        if (t + 1 < NNODE && g < D)
            mp_next = g_atomP[(d * NNODE + t + 1) * D + g];   // prefetch

        int4 pv = pred_sh[dl][t];
        float outv;
        bool has = (pv.x >= 0) | (pv.y >= 0) | (pv.z >= 0) | (pv.w >= 0);
        if (has) {
            float s0 = (pv.x >= 0) ? sdot_sh[dl][pv.x] : -3.0e38f;
            float s1 = (pv.y >= 0) ? sdot_sh[dl][pv.y] : -3.0e38f;
            float s2 = (pv.z >= 0) ? sdot_sh[dl][pv.z] : -3.0e38f;
            float s3 = (pv.w >= 0) ? sdot_sh[dl][pv.w] : -3.0e38f;
            float m = fmaxf(fmaxf(s0, s1), fmaxf(s2, s3));
            // fast exp: MUFU.EX2 path; sentinel -> -inf -> 0 (no slow path)
            float e0 = __expf(s0 - m);
            float e1 = __expf(s1 - m);
            float e2 = __expf(s2 - m);
            float e3 = __expf(s3 - m);
            float sum = (e0 + e1) + (e2 + e3);
            int p0 = pv.x < 0 ? 0 : pv.x;
            int p1 = pv.y < 0 ? 0 : pv.y;
            int p2 = pv.z < 0 ? 0 : pv.z;
            int p3 = pv.w < 0 ? 0 : pv.w;
            float za01 = e0 * z_sh[dl][p0][g] + e1 * z_sh[dl][p1][g];
            float za23 = e2 * z_sh[dl][p2][g] + e3 * z_sh[dl][p3][g];
            outv = fmaxf(mp + __fdividef(za01 + za23, sum), 0.f);
        } else if (g < D) {
            // rare (t=0 always; t>0 with p~0.0016): relu(W_single@atom + b)
            const float* arow = atoms + (d * NNODE + t) * D;   // uniform, bcast
            const float* wrow = W_single + g * D;               // L2-hot
            float acc = bsg[g];
#pragma unroll
            for (int k = 0; k < 31; k++) {
                float2 av = *(const float2*)(arow + 2 * k);
                float2 wv = *(const float2*)(wrow + 2 * k);
                acc += wv.x * av.x + wv.y * av.y;
            }
            outv = fmaxf(acc, 0.f);
        } else {
            outv = 0.f;
        }
        out_sh[dl][g] = (g < D) ? outv : 0.f;
        dag_bar(dl);

        if (g < D) {
            ull acc0 = 0ULL, acc1 = 0ULL, acc2 = 0ULL, acc3 = 0ULL;
#pragma unroll
            for (int k2 = 0; k2 < 32; k2 += 4) {   // 4 chains: dep len 8 not 16
                ulonglong2 oa = *(const ulonglong2*)&out_sh[dl][2 * k2];
                ulonglong2 ob = *(const ulonglong2*)&out_sh[dl][2 * k2 + 4];
                ffma2(acc0, Wr2[k2],     oa.x);
                ffma2(acc1, Wr2[k2 + 1], oa.y);
                ffma2(acc2, Wr2[k2 + 2], ob.x);
                ffma2(acc3, Wr2[k2 + 3], ob.y);
            }
            float2 f0 = unpack2(acc0), f1 = unpack2(acc1);
            float2 f2 = unpack2(acc2), f3 = unpack2(acc3);
            z_sh[dl][t][g] = ((f0.x + f0.y) + (f1.x + f1.y))
                           + ((f2.x + f2.y) + (f3.x + f3.y));
            if (t == NNODE - 1) g_last[d * D + g] = outv;
        } else if (g == D) {
            ull s0 = 0ULL, s1 = 0ULL;
#pragma unroll
            for (int k2 = 0; k2 < 32; k2 += 2) {
                ulonglong2 o = *(const ulonglong2*)&out_sh[dl][2 * k2];
                ffma2(s0, attw2[k2],     o.x);
                ffma2(s1, attw2[k2 + 1], o.y);
            }
            float2 f0 = unpack2(s0), f1 = unpack2(s1);
            sdot_sh[dl][t] = (f0.x + f0.y) + (f1.x + f1.y);
        }
        dag_bar(dl);
    }

    // fused logit: L[d] = out_47 . dag_w
    float lg = out_sh[dl][g] * dagw;
#pragma unroll
    for (int o = 16; o > 0; o >>= 1) lg += __shfl_xor_sync(0xffffffffu, lg, o);
    if ((tid & 31) == 0) red_sh[tid >> 5] = lg;
    dag_bar(dl);
    if (g == 0) {
        float L = red_sh[dl * 2] + red_sh[dl * 2 + 1];
        g_logit[d] = L;
        atomicMax(&g_maxbits, enc_f(L));   // no return use -> REDG.MAX
    }
}

// ============================================================================
// K3: partial softmax-pool. 256 blocks x 64 threads, 64 DAGs per block.
// ============================================================================
__global__ void __launch_bounds__(64) k_pool() {
    __shared__ float e_sh[64];
    int tid = threadIdx.x;
    long base = (long)blockIdx.x * 64;
    int mb = g_maxbits;
    float M = __int_as_float(mb >= 0 ? mb : (mb ^ 0x7FFFFFFF));
    e_sh[tid] = __expf(g_logit[base + tid] - M);
    __syncthreads();
    if (tid < D) {
        float pool = 0.f;
#pragma unroll 4
        for (int i = 0; i < 64; i++)
            pool += e_sh[i] * g_last[(base + i) * D + tid];
        g_part[blockIdx.x * 64 + tid] = pool;
    } else if (tid == D) {
        float sE = 0.f;
#pragma unroll
        for (int i = 0; i < 64; i++) sE += e_sh[i];
        g_part[blockIdx.x * 64 + D] = sE;
    }
}

// ============================================================================
// K4: reduce partials -> pooled; out = sigmoid(W_final @ pooled + b_final)
// ============================================================================
__global__ void __launch_bounds__(512) k_final(const float* __restrict__ W_final,
                                               const float* __restrict__ b_final,
                                               float* __restrict__ out) {
    __shared__ float part[8][64];
    __shared__ float pooled[64];
    int tid = threadIdx.x;
    int c = tid >> 6, col = tid & 63;
    float s = 0.f;
    for (int b = c; b < NPOOL; b += 8) s += g_part[b * 64 + col];
    part[c][col] = s;
    __syncthreads();
    if (tid < 64) {
        float t = 0.f;
#pragma unroll
        for (int i = 0; i < 8; i++) t += part[i][tid];
        pooled[tid] = t;            // pooled[62] = sumE
    }
    __syncthreads();
    float inv = 1.f / pooled[D];
    if (tid < NCLS) {
        float acc = 0.f;
#pragma unroll
        for (int k = 0; k < D; k++) acc += W_final[tid * D + k] * pooled[k];
        acc = b_final[tid] + acc * inv;
        out[tid] = 1.f / (1.f + expf(-acc));
    }
}

// ============================================================================
extern "C" void kernel_launch(void* const* d_in, const int* in_sizes, int n_in,
                              void* d_out, int out_size) {
    const float* atoms    = (const float*)d_in[0];
    const int*   preds    = (const int*)  d_in[1];
    const float* W_single = (const float*)d_in[2];
    const float* b_single = (const float*)d_in[3];
    const float* W_merge  = (const float*)d_in[4];
    const float* b_merge  = (const float*)d_in[5];
    const float* att_w    = (const float*)d_in[6];
    const float* dag_w    = (const float*)d_in[7];
    const float* W_final  = (const float*)d_in[8];
    const float* b_final  = (const float*)d_in[9];
    float* out = (float*)d_out;

    // positions 0,1 = padding so the ncu capture slot (4th launch) = k_scan
    k_nop<<<1, 32>>>();
    k_reset<<<1, 32>>>();
    k_atomP<<<NDAG * NNODE / 128, 128>>>(atoms, W_merge, b_merge);
    k_scan<<<NDAG / DPC, 128>>>(atoms, preds, W_single, b_single, W_merge, att_w, dag_w);
    k_pool<<<NPOOL, 64>>>();
    k_final<<<1, 512>>>(W_final, b_final, out);
}

// round 8
// speedup vs baseline: 1.1280x; 1.0091x over previous
#include <cuda_runtime.h>
#include <math.h>

#define NDAG  16384
#define NNODE 48
#define D     62
#define DP    64
#define NCLS  500
#define NPOOL 256   // pool partial blocks

typedef unsigned long long ull;

// -------- scratch (static device globals; no runtime allocation) ----------
__device__ float g_atomP[(size_t)NDAG * NNODE * D];  // W_merge[:,62:]@atom + b_merge
__device__ float g_last[(size_t)NDAG * D];           // sink outputs per DAG
__device__ float g_logit[NDAG];                      // last . dag_w
__device__ int   g_maxbits;                          // order-encoded max logit
__device__ float g_part[NPOOL * 64];                 // [c][0..61]=numerator, [62]=sumE

__device__ __forceinline__ int enc_f(float f) {
    int i = __float_as_int(f);
    return (i >= 0) ? i : (i ^ 0x7FFFFFFF);
}
// packed fp32x2 FMA (Blackwell FFMA2 — only reachable via PTX)
__device__ __forceinline__ void ffma2(ull& d, ull a, ull b) {
    asm("fma.rn.f32x2 %0, %1, %2, %0;" : "+l"(d) : "l"(a), "l"(b));
}
__device__ __forceinline__ ull pack2(float lo, float hi) {
    ull r;
    asm("mov.b64 %0, {%1, %2};" : "=l"(r)
        : "r"(__float_as_uint(lo)), "r"(__float_as_uint(hi)));
    return r;
}
__device__ __forceinline__ float2 unpack2(ull v) {
    unsigned lo, hi;
    asm("mov.b64 {%0, %1}, %2;" : "=r"(lo), "=r"(hi) : "l"(v));
    return make_float2(__uint_as_float(lo), __uint_as_float(hi));
}

// ============================================================================
// padding / reset so the ncu capture window (4th launch) lands on k_scan
// ============================================================================
__global__ void k_nop() {}
__global__ void k_reset() { if (threadIdx.x == 0) g_maxbits = 0x80000000; }

// ============================================================================
// K1: atomP[node,g] = b_merge[g] + sum_k W_merge[g][62+k] * atoms[node,k]
// Coalesced global I/O via pitch-63 smem staging; fp32x2 with 4 acc chains.
// ============================================================================
__global__ void __launch_bounds__(128) k_atomP(const float* __restrict__ atoms,
                                               const float* __restrict__ W_merge,
                                               const float* __restrict__ b_merge) {
    __shared__ __align__(16) float As[128 * 63];   // 128 node-rows, pitch 63
    __shared__ __align__(16) float Ws[D][DP];      // Ws[g][k] = W_merge[g][62+k]
    __shared__ float bs[DP];
    int tid = threadIdx.x;

    for (int i = tid; i < D * DP; i += 128) {
        int gg = i >> 6, k = i & 63;
        Ws[gg][k] = (k < D) ? W_merge[gg * (2 * D) + D + k] : 0.f;
    }
    if (tid < DP) bs[tid] = (tid < D) ? b_merge[tid] : 0.f;

    size_t base = (size_t)blockIdx.x * 128 * D;
    {   // coalesced load -> pitch-63 rows (incremental row/col: 128 = 2*62+4)
        unsigned row = (unsigned)tid / D, col = (unsigned)tid - row * D;
        unsigned idx = tid;
#pragma unroll 1
        for (int j = 0; j < D; j++) {
            As[row * 63 + col] = atoms[base + idx];
            idx += 128; row += 2; col += 4;
            if (col >= D) { col -= D; row++; }
        }
    }
    __syncthreads();

    ull a2[32];                                    // atom row packed f32x2
#pragma unroll
    for (int k = 0; k < 31; k++)
        a2[k] = pack2(As[tid * 63 + 2 * k], As[tid * 63 + 2 * k + 1]);
    a2[31] = 0ULL;
    __syncthreads();                               // As reused as output staging

#pragma unroll 2
    for (int gg = 0; gg < D; gg++) {
        ull acc0 = pack2(bs[gg], 0.f), acc1 = 0ULL, acc2 = 0ULL, acc3 = 0ULL;
#pragma unroll
        for (int k2 = 0; k2 < 32; k2 += 4) {       // 4 chains, dep dist 8 cyc
            ulonglong2 wa = *(const ulonglong2*)&Ws[gg][2 * k2];
            ulonglong2 wb = *(const ulonglong2*)&Ws[gg][2 * k2 + 4];
            ffma2(acc0, a2[k2],     wa.x);
            ffma2(acc1, a2[k2 + 1], wa.y);
            ffma2(acc2, a2[k2 + 2], wb.x);
            ffma2(acc3, a2[k2 + 3], wb.y);
        }
        float2 f0 = unpack2(acc0), f1 = unpack2(acc1);
        float2 f2 = unpack2(acc2), f3 = unpack2(acc3);
        As[tid * 63 + gg] = ((f0.x + f0.y) + (f1.x + f1.y))
                          + ((f2.x + f2.y) + (f3.x + f3.y));
    }
    __syncthreads();

    {   // coalesced store
        unsigned row = (unsigned)tid / D, col = (unsigned)tid - row * D;
        unsigned idx = tid;
#pragma unroll 1
        for (int j = 0; j < D; j++) {
            g_atomP[base + idx] = As[row * 63 + col];
            idx += 128; row += 2; col += 4;
            if (col >= D) { col -= D; row++; }
        }
    }
}

// ============================================================================
// K2: sequential DAG scan. 1 DAG/CTA, 128 threads: thread (g,h) = output dim
// g = tid>>1, k-half h = tid&1. Split-K halves W regs (32 vs 64) -> 2x occ.
// Thread pair g==62 computes sdot via the same matvec path (Wr2 = att_w).
// ============================================================================
__global__ void __launch_bounds__(128) k_scan(const float* __restrict__ atoms,
                                              const int*   __restrict__ preds,
                                              const float* __restrict__ W_single,
                                              const float* __restrict__ b_single,
                                              const float* __restrict__ W_merge,
                                              const float* __restrict__ att_w,
                                              const float* __restrict__ dag_w) {
    __shared__ float z_sh[NNODE * DP];
    __shared__ __align__(16) float out_sh[DP];
    __shared__ float sdot_sh[NNODE];
    __shared__ int4  pred_sh[NNODE];
    __shared__ float red_sh[4];

    int tid = threadIdx.x;
    int g = tid >> 1, h = tid & 1;
    long d = blockIdx.x;

    {   // preds for this DAG, coalesced
        const int* src = preds + d * NNODE * 4;
        int* dst = (int*)pred_sh;
        for (int i = tid; i < NNODE * 4; i += 128) dst[i] = src[i];
    }

    // half-row of W_agg (or att_w for g==62) packed f32x2: 16 ull = 32 regs
    ull Wr2[16];
    if (g < D) {
        const float* wrow = W_merge + (long)g * (2 * D);
#pragma unroll
        for (int j = 0; j < 16; j++) {
            int k = h * 32 + 2 * j;
            float lo = (k     < D) ? wrow[k]     : 0.f;
            float hi = (k + 1 < D) ? wrow[k + 1] : 0.f;
            Wr2[j] = pack2(lo, hi);
        }
    } else if (g == D) {
#pragma unroll
        for (int j = 0; j < 16; j++) {
            int k = h * 32 + 2 * j;
            float lo = (k     < D) ? att_w[k]     : 0.f;
            float hi = (k + 1 < D) ? att_w[k + 1] : 0.f;
            Wr2[j] = pack2(lo, hi);
        }
    } else {
#pragma unroll
        for (int j = 0; j < 16; j++) Wr2[j] = 0ULL;
    }
    float dagw_t = (tid < D) ? dag_w[tid] : 0.f;
    __syncthreads();

    bool ldmp = (h == 0) && (g < D);
    float mp_next = ldmp ? g_atomP[d * NNODE * D + g] : 0.f;

#pragma unroll 1
    for (int t = 0; t < NNODE; t++) {
        float mp = mp_next;
        if (t + 1 < NNODE && ldmp)
            mp_next = g_atomP[(d * NNODE + t + 1) * D + g];   // prefetch

        int4 pv = pred_sh[t];                                 // CTA-uniform
        float outv = 0.f;
        bool has = (pv.x >= 0) | (pv.y >= 0) | (pv.z >= 0) | (pv.w >= 0);
        if (has) {
            float s0 = (pv.x >= 0) ? sdot_sh[pv.x] : -3.0e38f;
            float s1 = (pv.y >= 0) ? sdot_sh[pv.y] : -3.0e38f;
            float s2 = (pv.z >= 0) ? sdot_sh[pv.z] : -3.0e38f;
            float s3 = (pv.w >= 0) ? sdot_sh[pv.w] : -3.0e38f;
            float m = fmaxf(fmaxf(s0, s1), fmaxf(s2, s3));
            float e0 = __expf(s0 - m);
            float e1 = __expf(s1 - m);
            float e2 = __expf(s2 - m);
            float e3 = __expf(s3 - m);
            float sum = (e0 + e1) + (e2 + e3);
            // split gather: half h handles preds 2h, 2h+1
            float e_a = h ? e2 : e0;
            float e_b = h ? e3 : e1;
            int   p_a = h ? (pv.z < 0 ? 0 : pv.z) : (pv.x < 0 ? 0 : pv.x);
            int   p_b = h ? (pv.w < 0 ? 0 : pv.w) : (pv.y < 0 ? 0 : pv.y);
            float za_h = (g < D) ? (e_a * z_sh[p_a * DP + g]
                                  + e_b * z_sh[p_b * DP + g]) : 0.f;
            float za = za_h + __shfl_xor_sync(0xffffffffu, za_h, 1);
            outv = (g < D) ? fmaxf(mp + __fdividef(za, sum), 0.f) : 0.f;
        } else if (h == 0 && g < D) {
            // rare (t=0 always; t>0 with p~0.0016): relu(W_single@atom + b)
            const float* arow = atoms + (d * NNODE + t) * D;   // bcast, L2-hot
            const float* wrow = W_single + g * D;
            float acc = b_single[g];
#pragma unroll
            for (int k = 0; k < 31; k++) {
                float2 av = *(const float2*)(arow + 2 * k);
                float2 wv = *(const float2*)(wrow + 2 * k);
                acc += wv.x * av.x + wv.y * av.y;
            }
            outv = fmaxf(acc, 0.f);
        }
        if (h == 0) out_sh[g] = (g < D) ? outv : 0.f;
        __syncthreads();

        {   // half-dot: z[t][g] (g<62) or sdot[t] (g==62)
            const ull* o2 = (const ull*)out_sh + h * 16;
            ull a0 = 0ULL, a1 = 0ULL, a2v = 0ULL, a3 = 0ULL;
#pragma unroll
            for (int j = 0; j < 16; j += 4) {
                ulonglong2 oa = *(const ulonglong2*)(o2 + j);
                ulonglong2 ob = *(const ulonglong2*)(o2 + j + 2);
                ffma2(a0,  Wr2[j],     oa.x);
                ffma2(a1,  Wr2[j + 1], oa.y);
                ffma2(a2v, Wr2[j + 2], ob.x);
                ffma2(a3,  Wr2[j + 3], ob.y);
            }
            float2 f0 = unpack2(a0), f1 = unpack2(a1);
            float2 f2 = unpack2(a2v), f3 = unpack2(a3);
            float part = ((f0.x + f0.y) + (f1.x + f1.y))
                       + ((f2.x + f2.y) + (f3.x + f3.y));
            float tot = part + __shfl_xor_sync(0xffffffffu, part, 1);
            if (h == 0) {
                if (g < D)       z_sh[t * DP + g] = tot;
                else if (g == D) sdot_sh[t] = tot;
            }
        }
        if (t == NNODE - 1 && h == 0 && g < D) g_last[d * D + g] = outv;
        __syncthreads();
    }

    // fused logit: L[d] = out_47 . dag_w  (out_sh still holds final outputs)
    float lg = (tid < D) ? out_sh[tid] * dagw_t : 0.f;
#pragma unroll
    for (int o = 16; o > 0; o >>= 1) lg += __shfl_xor_sync(0xffffffffu, lg, o);
    if ((tid & 31) == 0) red_sh[tid >> 5] = lg;
    __syncthreads();
    if (tid == 0) {
        float L = (red_sh[0] + red_sh[1]) + (red_sh[2] + red_sh[3]);
        g_logit[d] = L;
        atomicMax(&g_maxbits, enc_f(L));
    }
}

// ============================================================================
// K3: partial softmax-pool. 256 blocks x 64 threads, 64 DAGs per block.
// ============================================================================
__global__ void __launch_bounds__(64) k_pool() {
    __shared__ float e_sh[64];
    int tid = threadIdx.x;
    long base = (long)blockIdx.x * 64;
    int mb = g_maxbits;
    float M = __int_as_float(mb >= 0 ? mb : (mb ^ 0x7FFFFFFF));
    e_sh[tid] = __expf(g_logit[base + tid] - M);
    __syncthreads();
    if (tid < D) {
        float pool = 0.f;
#pragma unroll 4
        for (int i = 0; i < 64; i++)
            pool += e_sh[i] * g_last[(base + i) * D + tid];
        g_part[blockIdx.x * 64 + tid] = pool;
    } else if (tid == D) {
        float sE = 0.f;
#pragma unroll
        for (int i = 0; i < 64; i++) sE += e_sh[i];
        g_part[blockIdx.x * 64 + D] = sE;
    }
}

// ============================================================================
// K4: reduce partials -> pooled; out = sigmoid(W_final @ pooled + b_final)
// ============================================================================
__global__ void __launch_bounds__(512) k_final(const float* __restrict__ W_final,
                                               const float* __restrict__ b_final,
                                               float* __restrict__ out) {
    __shared__ float part[8][64];
    __shared__ float pooled[64];
    int tid = threadIdx.x;
    int c = tid >> 6, col = tid & 63;
    float s = 0.f;
    for (int b = c; b < NPOOL; b += 8) s += g_part[b * 64 + col];
    part[c][col] = s;
    __syncthreads();
    if (tid < 64) {
        float t = 0.f;
#pragma unroll
        for (int i = 0; i < 8; i++) t += part[i][tid];
        pooled[tid] = t;            // pooled[62] = sumE
    }
    __syncthreads();
    float inv = 1.f / pooled[D];
    if (tid < NCLS) {
        float acc = 0.f;
#pragma unroll
        for (int k = 0; k < D; k++) acc += W_final[tid * D + k] * pooled[k];
        acc = b_final[tid] + acc * inv;
        out[tid] = 1.f / (1.f + expf(-acc));
    }
}

// ============================================================================
extern "C" void kernel_launch(void* const* d_in, const int* in_sizes, int n_in,
                              void* d_out, int out_size) {
    const float* atoms    = (const float*)d_in[0];
    const int*   preds    = (const int*)  d_in[1];
    const float* W_single = (const float*)d_in[2];
    const float* b_single = (const float*)d_in[3];
    const float* W_merge  = (const float*)d_in[4];
    const float* b_merge  = (const float*)d_in[5];
    const float* att_w    = (const float*)d_in[6];
    const float* dag_w    = (const float*)d_in[7];
    const float* W_final  = (const float*)d_in[8];
    const float* b_final  = (const float*)d_in[9];
    float* out = (float*)d_out;

    // positions 0,1 = padding so the ncu capture slot (4th launch) = k_scan
    k_nop<<<1, 32>>>();
    k_reset<<<1, 32>>>();
    k_atomP<<<NDAG * NNODE / 128, 128>>>(atoms, W_merge, b_merge);
    k_scan<<<NDAG, 128>>>(atoms, preds, W_single, b_single, W_merge, att_w, dag_w);
    k_pool<<<NPOOL, 64>>>();
    k_final<<<1, 512>>>(W_final, b_final, out);
}

// round 9
// speedup vs baseline: 1.2375x; 1.0971x over previous
#include <cuda_runtime.h>
#include <math.h>

#define NDAG  16384
#define NNODE 48
#define D     62
#define DP    64
#define NCLS  500
#define NPOOL 256   // pool partial blocks

typedef unsigned long long ull;

// -------- scratch (static device globals; no runtime allocation) ----------
__device__ float g_atomP[(size_t)NDAG * NNODE * D];  // W_merge[:,62:]@atom + b_merge
__device__ float g_last[(size_t)NDAG * D];           // sink outputs per DAG
__device__ float g_logit[NDAG];                      // last . dag_w
__device__ int   g_maxbits;                          // order-encoded max logit
__device__ float g_part[NPOOL * 64];                 // [c][0..61]=numerator, [62]=sumE

__device__ __forceinline__ int enc_f(float f) {
    int i = __float_as_int(f);
    return (i >= 0) ? i : (i ^ 0x7FFFFFFF);
}
// packed fp32x2 FMA (Blackwell FFMA2 — only reachable via PTX)
__device__ __forceinline__ void ffma2(ull& d, ull a, ull b) {
    asm("fma.rn.f32x2 %0, %1, %2, %0;" : "+l"(d) : "l"(a), "l"(b));
}
__device__ __forceinline__ ull pack2(float lo, float hi) {
    ull r;
    asm("mov.b64 %0, {%1, %2};" : "=l"(r)
        : "r"(__float_as_uint(lo)), "r"(__float_as_uint(hi)));
    return r;
}
__device__ __forceinline__ float2 unpack2(ull v) {
    unsigned lo, hi;
    asm("mov.b64 {%0, %1}, %2;" : "=r"(lo), "=r"(hi) : "l"(v));
    return make_float2(__uint_as_float(lo), __uint_as_float(hi));
}
__device__ __forceinline__ float ex2a(float x) {   // raw MUFU.EX2
    float r; asm("ex2.approx.ftz.f32 %0, %1;" : "=f"(r) : "f"(x)); return r;
}
#define LOG2E 1.4426950408889634f

// interleaved out layout: k -> float index ((k&31)>>2)*8 + (k>>5)*4 + (k&3)
__device__ __forceinline__ int oidx(int k) {
    return ((k & 31) >> 2) * 8 + (k >> 5) * 4 + (k & 3);
}

// ============================================================================
// padding / reset; launch order puts k_atomP in the ncu capture slot (4th)
// ============================================================================
__global__ void k_nop() {}
__global__ void k_reset() { if (threadIdx.x == 0) g_maxbits = 0x80000000; }

// ============================================================================
// K1: atomP[node,g] = b_merge[g] + sum_k W_merge[g][62+k] * atoms[node,k]
// (unchanged this round — being profiled in capture slot 4)
// ============================================================================
__global__ void __launch_bounds__(128) k_atomP(const float* __restrict__ atoms,
                                               const float* __restrict__ W_merge,
                                               const float* __restrict__ b_merge) {
    __shared__ __align__(16) float As[128 * 63];   // 128 node-rows, pitch 63
    __shared__ __align__(16) float Ws[D][DP];      // Ws[g][k] = W_merge[g][62+k]
    __shared__ float bs[DP];
    int tid = threadIdx.x;

    for (int i = tid; i < D * DP; i += 128) {
        int gg = i >> 6, k = i & 63;
        Ws[gg][k] = (k < D) ? W_merge[gg * (2 * D) + D + k] : 0.f;
    }
    if (tid < DP) bs[tid] = (tid < D) ? b_merge[tid] : 0.f;

    size_t base = (size_t)blockIdx.x * 128 * D;
    {   // coalesced load -> pitch-63 rows (incremental row/col: 128 = 2*62+4)
        unsigned row = (unsigned)tid / D, col = (unsigned)tid - row * D;
        unsigned idx = tid;
#pragma unroll 1
        for (int j = 0; j < D; j++) {
            As[row * 63 + col] = atoms[base + idx];
            idx += 128; row += 2; col += 4;
            if (col >= D) { col -= D; row++; }
        }
    }
    __syncthreads();

    ull a2[32];
#pragma unroll
    for (int k = 0; k < 31; k++)
        a2[k] = pack2(As[tid * 63 + 2 * k], As[tid * 63 + 2 * k + 1]);
    a2[31] = 0ULL;
    __syncthreads();                               // As reused as output staging

#pragma unroll 2
    for (int gg = 0; gg < D; gg++) {
        ull acc0 = pack2(bs[gg], 0.f), acc1 = 0ULL, acc2 = 0ULL, acc3 = 0ULL;
#pragma unroll
        for (int k2 = 0; k2 < 32; k2 += 4) {
            ulonglong2 wa = *(const ulonglong2*)&Ws[gg][2 * k2];
            ulonglong2 wb = *(const ulonglong2*)&Ws[gg][2 * k2 + 4];
            ffma2(acc0, a2[k2],     wa.x);
            ffma2(acc1, a2[k2 + 1], wa.y);
            ffma2(acc2, a2[k2 + 2], wb.x);
            ffma2(acc3, a2[k2 + 3], wb.y);
        }
        float2 f0 = unpack2(acc0), f1 = unpack2(acc1);
        float2 f2 = unpack2(acc2), f3 = unpack2(acc3);
        As[tid * 63 + gg] = ((f0.x + f0.y) + (f1.x + f1.y))
                          + ((f2.x + f2.y) + (f3.x + f3.y));
    }
    __syncthreads();

    {   // coalesced store
        unsigned row = (unsigned)tid / D, col = (unsigned)tid - row * D;
        unsigned idx = tid;
#pragma unroll 1
        for (int j = 0; j < D; j++) {
            g_atomP[base + idx] = As[row * 63 + col];
            idx += 128; row += 2; col += 4;
            if (col >= D) { col -= D; row++; }
        }
    }
}

// ============================================================================
// K2: sequential DAG scan. 1 DAG/CTA; thread (g,h): g=tid>>1, h=tid&1.
// out vector stored 16B-interleaved by k-half so paired lanes hit one
// 128B line per LDS.128 (1 wavefront, was 2). preds remapped (-1 -> 48,
// sentinel row), sdot pre-scaled by log2e for raw ex2.approx.
// ============================================================================
__global__ void __launch_bounds__(128) k_scan(const float* __restrict__ atoms,
                                              const int*   __restrict__ preds,
                                              const float* __restrict__ W_single,
                                              const float* __restrict__ b_single,
                                              const float* __restrict__ W_merge,
                                              const float* __restrict__ att_w,
                                              const float* __restrict__ dag_w) {
    __shared__ float z_sh[(NNODE + 1) * DP];       // +1 sentinel row (zeroed)
    __shared__ __align__(16) float out_sh[DP];     // interleaved layout
    __shared__ float sdot_sh[NNODE + 1];           // pre-scaled by log2e
    __shared__ int4  pred_sh[NNODE];
    __shared__ float red_sh[4];

    int tid = threadIdx.x;
    int g = tid >> 1, h = tid & 1;
    long d = blockIdx.x;

    {   // preds for this DAG: coalesced load + remap (-1 -> 48)
        const int* src = preds + d * NNODE * 4;
        int* dst = (int*)pred_sh;
        for (int i = tid; i < NNODE * 4; i += 128) {
            int v = src[i];
            dst[i] = (v < 0) ? NNODE : v;
        }
    }
    if (tid < DP) z_sh[NNODE * DP + tid] = 0.f;    // sentinel z row
    if (tid == 0) sdot_sh[NNODE] = -1e30f;         // sentinel logit

    // half-row of W_agg (att_w for g==62) packed to match interleaved order
    ull Wr2[16];
    {
        const float* wrow = (g < D)  ? (W_merge + (long)g * (2 * D)) :
                            (g == D) ? att_w : (const float*)0;
#pragma unroll
        for (int jj = 0; jj < 8; jj++) {
#pragma unroll
            for (int q = 0; q < 2; q++) {
                int k0 = h * 32 + 4 * jj + 2 * q;
                float lo = (wrow && k0     < D) ? wrow[k0]     : 0.f;
                float hi = (wrow && k0 + 1 < D) ? wrow[k0 + 1] : 0.f;
                Wr2[2 * jj + q] = pack2(lo, hi);
            }
        }
    }
    float dagw_t = (tid < D) ? dag_w[tid] : 0.f;
    int my_oidx = oidx(g);                         // interleaved store slot
    __syncthreads();

    bool ldmp = (h == 0) && (g < D);
    float mp_next = ldmp ? g_atomP[d * NNODE * D + g] : 0.f;

#pragma unroll 1
    for (int t = 0; t < NNODE; t++) {
        float mp = mp_next;
        if (t + 1 < NNODE && ldmp)
            mp_next = g_atomP[(d * NNODE + t + 1) * D + g];   // prefetch

        int4 pv = pred_sh[t];                                 // CTA-uniform
        float outv = 0.f;
        bool has = (pv.x + pv.y + pv.z + pv.w) != 4 * NNODE;  // any valid
        if (has) {
            float s0 = sdot_sh[pv.x];
            float s1 = sdot_sh[pv.y];
            float s2 = sdot_sh[pv.z];
            float s3 = sdot_sh[pv.w];
            float m = fmaxf(fmaxf(s0, s1), fmaxf(s2, s3));
            float e0 = ex2a(s0 - m);
            float e1 = ex2a(s1 - m);
            float e2 = ex2a(s2 - m);
            float e3 = ex2a(s3 - m);
            float sum = (e0 + e1) + (e2 + e3);
            float e_a = h ? e2 : e0;
            float e_b = h ? e3 : e1;
            int   p_a = h ? pv.z : pv.x;
            int   p_b = h ? pv.w : pv.y;
            float za_h = (g < D) ? (e_a * z_sh[p_a * DP + g]
                                  + e_b * z_sh[p_b * DP + g]) : 0.f;
            float za = za_h + __shfl_xor_sync(0xffffffffu, za_h, 1);
            outv = (g < D) ? fmaxf(mp + __fdividef(za, sum), 0.f) : 0.f;
        } else if (h == 0 && g < D) {
            // rare (t=0 always; t>0 with p~0.0016): relu(W_single@atom + b)
            const float* arow = atoms + (d * NNODE + t) * D;   // bcast, L2-hot
            const float* wrow = W_single + g * D;
            float acc = b_single[g];
#pragma unroll
            for (int k = 0; k < 31; k++) {
                float2 av = *(const float2*)(arow + 2 * k);
                float2 wv = *(const float2*)(wrow + 2 * k);
                acc += wv.x * av.x + wv.y * av.y;
            }
            outv = fmaxf(acc, 0.f);
        }
        if (h == 0) out_sh[my_oidx] = (g < D) ? outv : 0.f;   // interleaved
        __syncthreads();

        {   // half-dot via interleaved reads: lanes' pair hits ONE 128B line
            ull a0 = 0ULL, a1 = 0ULL, a2v = 0ULL, a3 = 0ULL;
            const char* ob = (const char*)out_sh + h * 16;
#pragma unroll
            for (int jj = 0; jj < 8; jj += 2) {
                ulonglong2 oa = *(const ulonglong2*)(ob + 32 * jj);
                ulonglong2 oc = *(const ulonglong2*)(ob + 32 * (jj + 1));
                ffma2(a0,  Wr2[2 * jj],     oa.x);
                ffma2(a1,  Wr2[2 * jj + 1], oa.y);
                ffma2(a2v, Wr2[2 * jj + 2], oc.x);
                ffma2(a3,  Wr2[2 * jj + 3], oc.y);
            }
            float2 f0 = unpack2(a0), f1 = unpack2(a1);
            float2 f2 = unpack2(a2v), f3 = unpack2(a3);
            float part = ((f0.x + f0.y) + (f1.x + f1.y))
                       + ((f2.x + f2.y) + (f3.x + f3.y));
            float tot = part + __shfl_xor_sync(0xffffffffu, part, 1);
            if (h == 0) {
                if (g < D)       z_sh[t * DP + g] = tot;
                else if (g == D) sdot_sh[t] = tot * LOG2E;   // pre-scaled
            }
        }
        if (t == NNODE - 1 && h == 0 && g < D) g_last[d * D + g] = outv;
        __syncthreads();
    }

    // fused logit: L[d] = out_47 . dag_w  (out_sh interleaved)
    float lg = (tid < D) ? out_sh[oidx(tid)] * dagw_t : 0.f;
#pragma unroll
    for (int o = 16; o > 0; o >>= 1) lg += __shfl_xor_sync(0xffffffffu, lg, o);
    if ((tid & 31) == 0) red_sh[tid >> 5] = lg;
    __syncthreads();
    if (tid == 0) {
        float L = (red_sh[0] + red_sh[1]) + (red_sh[2] + red_sh[3]);
        g_logit[d] = L;
        atomicMax(&g_maxbits, enc_f(L));
    }
}

// ============================================================================
// K3: partial softmax-pool. 256 blocks x 64 threads, 64 DAGs per block.
// ============================================================================
__global__ void __launch_bounds__(64) k_pool() {
    __shared__ float e_sh[64];
    int tid = threadIdx.x;
    long base = (long)blockIdx.x * 64;
    int mb = g_maxbits;
    float M = __int_as_float(mb >= 0 ? mb : (mb ^ 0x7FFFFFFF));
    e_sh[tid] = __expf(g_logit[base + tid] - M);
    __syncthreads();
    if (tid < D) {
        float pool = 0.f;
#pragma unroll 4
        for (int i = 0; i < 64; i++)
            pool += e_sh[i] * g_last[(base + i) * D + tid];
        g_part[blockIdx.x * 64 + tid] = pool;
    } else if (tid == D) {
        float sE = 0.f;
#pragma unroll
        for (int i = 0; i < 64; i++) sE += e_sh[i];
        g_part[blockIdx.x * 64 + D] = sE;
    }
}

// ============================================================================
// K4: reduce partials -> pooled; out = sigmoid(W_final @ pooled + b_final)
// ============================================================================
__global__ void __launch_bounds__(512) k_final(const float* __restrict__ W_final,
                                               const float* __restrict__ b_final,
                                               float* __restrict__ out) {
    __shared__ float part[8][64];
    __shared__ float pooled[64];
    int tid = threadIdx.x;
    int c = tid >> 6, col = tid & 63;
    float s = 0.f;
    for (int b = c; b < NPOOL; b += 8) s += g_part[b * 64 + col];
    part[c][col] = s;
    __syncthreads();
    if (tid < 64) {
        float t = 0.f;
#pragma unroll
        for (int i = 0; i < 8; i++) t += part[i][tid];
        pooled[tid] = t;            // pooled[62] = sumE
    }
    __syncthreads();
    float inv = 1.f / pooled[D];
    if (tid < NCLS) {
        float acc = 0.f;
#pragma unroll
        for (int k = 0; k < D; k++) acc += W_final[tid * D + k] * pooled[k];
        acc = b_final[tid] + acc * inv;
        out[tid] = 1.f / (1.f + expf(-acc));
    }
}

// ============================================================================
extern "C" void kernel_launch(void* const* d_in, const int* in_sizes, int n_in,
                              void* d_out, int out_size) {
    const float* atoms    = (const float*)d_in[0];
    const int*   preds    = (const int*)  d_in[1];
    const float* W_single = (const float*)d_in[2];
    const float* b_single = (const float*)d_in[3];
    const float* W_merge  = (const float*)d_in[4];
    const float* b_merge  = (const float*)d_in[5];
    const float* att_w    = (const float*)d_in[6];
    const float* dag_w    = (const float*)d_in[7];
    const float* W_final  = (const float*)d_in[8];
    const float* b_final  = (const float*)d_in[9];
    float* out = (float*)d_out;

    // capture slot = 4th launch -> k_atomP this round (finally profile it)
    k_nop<<<1, 32>>>();
    k_reset<<<1, 32>>>();
    k_nop<<<1, 32>>>();
    k_atomP<<<NDAG * NNODE / 128, 128>>>(atoms, W_merge, b_merge);
    k_scan<<<NDAG, 128>>>(atoms, preds, W_single, b_single, W_merge, att_w, dag_w);
    k_pool<<<NPOOL, 64>>>();
    k_final<<<1, 512>>>(W_final, b_final, out);
}

// round 11
// speedup vs baseline: 1.3902x; 1.1234x over previous
#include <cuda_runtime.h>
#include <math.h>

#define NDAG  16384
#define NNODE 48
#define D     62
#define DP    64
#define NCLS  500
#define NPOOL 256   // pool partial blocks

typedef unsigned long long ull;

// -------- scratch (static device globals; no runtime allocation) ----------
__device__ float g_atomP[(size_t)NDAG * NNODE * D];  // W_merge[:,62:]@atom + b_merge
__device__ float g_last[(size_t)NDAG * D];           // sink outputs per DAG
__device__ float g_logit[NDAG];                      // last . dag_w
__device__ int   g_maxbits;                          // order-encoded max logit
__device__ float g_part[NPOOL * 64];                 // [c][0..61]=numerator, [62]=sumE

__device__ __forceinline__ int enc_f(float f) {
    int i = __float_as_int(f);
    return (i >= 0) ? i : (i ^ 0x7FFFFFFF);
}
// packed fp32x2 FMA (Blackwell FFMA2 — only reachable via PTX)
__device__ __forceinline__ void ffma2(ull& d, ull a, ull b) {
    asm("fma.rn.f32x2 %0, %1, %2, %0;" : "+l"(d) : "l"(a), "l"(b));
}
__device__ __forceinline__ ull pack2(float lo, float hi) {
    ull r;
    asm("mov.b64 %0, {%1, %2};" : "=l"(r)
        : "r"(__float_as_uint(lo)), "r"(__float_as_uint(hi)));
    return r;
}
__device__ __forceinline__ float2 unpack2(ull v) {
    unsigned lo, hi;
    asm("mov.b64 {%0, %1}, %2;" : "=r"(lo), "=r"(hi) : "l"(v));
    return make_float2(__uint_as_float(lo), __uint_as_float(hi));
}
__device__ __forceinline__ float ex2a(float x) {   // raw MUFU.EX2
    float r; asm("ex2.approx.ftz.f32 %0, %1;" : "=f"(r) : "f"(x)); return r;
}
#define LOG2E 1.4426950408889634f

// interleaved out layout: k -> float index ((k&31)>>2)*8 + (k>>5)*4 + (k&3)
__device__ __forceinline__ int oidx(int k) {
    return ((k & 31) >> 2) * 8 + (k >> 5) * 4 + (k & 3);
}

// ============================================================================
// padding / reset; launch order keeps k_atomP in the ncu capture slot (4th)
// ============================================================================
__global__ void k_nop() {}
__global__ void k_reset() { if (threadIdx.x == 0) g_maxbits = 0x80000000; }

// ============================================================================
// K1: atomP[node,g] = b_merge[g] + sum_k W_merge[g][62+k] * atoms[node,k]
// Split-K: 256 threads, thread pair (r = tid>>1 node row, h = tid&1 k-half).
// Half atom row in regs (a2[16] = 32 regs, was 64), W tile 16B-interleaved
// by k-half so a pair's LDS.128 touches one 32B span (1 wavefront).
// ============================================================================
__global__ void __launch_bounds__(256) k_atomP(const float* __restrict__ atoms,
                                               const float* __restrict__ W_merge,
                                               const float* __restrict__ b_merge) {
    __shared__ __align__(16) float As[128 * 63];   // staging + output, pitch 63
    __shared__ __align__(16) float Wsi[D * DP];    // interleaved by k-half
    __shared__ float bs[DP];
    int tid = threadIdx.x;
    int r = tid >> 1, h = tid & 1;

    // W_merge[:,62:] -> interleaved: orig chunk c=k>>2 stored at slot
    // 2*(c&7)+(c>>3); thread h's j-th 16B load returns chunk 8h+j.
    for (int i = tid; i < D * DP; i += 256) {
        int gg = i >> 6, k = i & 63;
        int c = k >> 2, pos = k & 3;
        int slot = 2 * (c & 7) + (c >> 3);
        Wsi[gg * DP + slot * 4 + pos] = (k < D) ? W_merge[gg * (2 * D) + D + k] : 0.f;
    }
    if (tid < DP) bs[tid] = (tid < D) ? b_merge[tid] : 0.f;

    size_t base = (size_t)blockIdx.x * 128 * D;
    {   // coalesced load -> pitch-63 rows (256 = 4*62 + 8)
        unsigned row = (unsigned)tid / D, col = (unsigned)tid - row * D;
        unsigned idx = tid;
#pragma unroll 1
        for (int j = 0; j < 31; j++) {
            As[row * 63 + col] = atoms[base + idx];
            idx += 256; row += 4; col += 8;
            if (col >= D) { col -= D; row++; }
        }
    }
    __syncthreads();

    // half atom row packed f32x2: floats [32h .. 32h+31] (h=1: last pair pad)
    ull a2[16];
    {
        const float* arow = As + r * 63 + 32 * h;
#pragma unroll
        for (int m = 0; m < 15; m++) a2[m] = pack2(arow[2 * m], arow[2 * m + 1]);
        a2[15] = h ? 0ULL : pack2(arow[30], arow[31]);
    }
    __syncthreads();                               // As reused as output staging

#pragma unroll 2
    for (int gg = 0; gg < D; gg++) {
        const ulonglong2* wb = (const ulonglong2*)(Wsi + gg * DP) + h;
        ull c0 = 0ULL, c1 = 0ULL, c2 = 0ULL, c3 = 0ULL;
#pragma unroll
        for (int j = 0; j < 8; j += 2) {
            ulonglong2 wA = wb[2 * j];             // slot 2j+h   (one 32B span/pair)
            ulonglong2 wB = wb[2 * (j + 1)];       // slot 2j+2+h
            ffma2(c0, a2[2 * j],     wA.x);
            ffma2(c1, a2[2 * j + 1], wA.y);
            ffma2(c2, a2[2 * j + 2], wB.x);
            ffma2(c3, a2[2 * j + 3], wB.y);
        }
        float2 f0 = unpack2(c0), f1 = unpack2(c1);
        float2 f2 = unpack2(c2), f3 = unpack2(c3);
        float part = ((f0.x + f0.y) + (f1.x + f1.y))
                   + ((f2.x + f2.y) + (f3.x + f3.y));
        float tot = part + __shfl_xor_sync(0xffffffffu, part, 1);
        if (h == 0) As[r * 63 + gg] = tot + bs[gg];
    }
    __syncthreads();

    {   // coalesced store
        unsigned row = (unsigned)tid / D, col = (unsigned)tid - row * D;
        unsigned idx = tid;
#pragma unroll 1
        for (int j = 0; j < 31; j++) {
            g_atomP[base + idx] = As[row * 63 + col];
            idx += 256; row += 4; col += 8;
            if (col >= D) { col -= D; row++; }
        }
    }
}

// ============================================================================
// K2: sequential DAG scan. 1 DAG/CTA; thread (g,h): g=tid>>1, h=tid&1.
// (unchanged from R9 — validated at ~575us)
// ============================================================================
__global__ void __launch_bounds__(128) k_scan(const float* __restrict__ atoms,
                                              const int*   __restrict__ preds,
                                              const float* __restrict__ W_single,
                                              const float* __restrict__ b_single,
                                              const float* __restrict__ W_merge,
                                              const float* __restrict__ att_w,
                                              const float* __restrict__ dag_w) {
    __shared__ float z_sh[(NNODE + 1) * DP];       // +1 sentinel row (zeroed)
    __shared__ __align__(16) float out_sh[DP];     // interleaved layout
    __shared__ float sdot_sh[NNODE + 1];           // pre-scaled by log2e
    __shared__ int4  pred_sh[NNODE];
    __shared__ float red_sh[4];

    int tid = threadIdx.x;
    int g = tid >> 1, h = tid & 1;
    long d = blockIdx.x;

    {   // preds for this DAG: coalesced load + remap (-1 -> 48)
        const int* src = preds + d * NNODE * 4;
        int* dst = (int*)pred_sh;
        for (int i = tid; i < NNODE * 4; i += 128) {
            int v = src[i];
            dst[i] = (v < 0) ? NNODE : v;
        }
    }
    if (tid < DP) z_sh[NNODE * DP + tid] = 0.f;    // sentinel z row
    if (tid == 0) sdot_sh[NNODE] = -1e30f;         // sentinel logit

    // half-row of W_agg (att_w for g==62) packed to match interleaved order
    ull Wr2[16];
    {
        const float* wrow = (g < D)  ? (W_merge + (long)g * (2 * D)) :
                            (g == D) ? att_w : (const float*)0;
#pragma unroll
        for (int jj = 0; jj < 8; jj++) {
#pragma unroll
            for (int q = 0; q < 2; q++) {
                int k0 = h * 32 + 4 * jj + 2 * q;
                float lo = (wrow && k0     < D) ? wrow[k0]     : 0.f;
                float hi = (wrow && k0 + 1 < D) ? wrow[k0 + 1] : 0.f;
                Wr2[2 * jj + q] = pack2(lo, hi);
            }
        }
    }
    float dagw_t = (tid < D) ? dag_w[tid] : 0.f;
    int my_oidx = oidx(g);                         // interleaved store slot
    __syncthreads();

    bool ldmp = (h == 0) && (g < D);
    float mp_next = ldmp ? g_atomP[d * NNODE * D + g] : 0.f;

#pragma unroll 1
    for (int t = 0; t < NNODE; t++) {
        float mp = mp_next;
        if (t + 1 < NNODE && ldmp)
            mp_next = g_atomP[(d * NNODE + t + 1) * D + g];   // prefetch

        int4 pv = pred_sh[t];                                 // CTA-uniform
        float outv = 0.f;
        bool has = (pv.x + pv.y + pv.z + pv.w) != 4 * NNODE;  // any valid
        if (has) {
            float s0 = sdot_sh[pv.x];
            float s1 = sdot_sh[pv.y];
            float s2 = sdot_sh[pv.z];
            float s3 = sdot_sh[pv.w];
            float m = fmaxf(fmaxf(s0, s1), fmaxf(s2, s3));
            float e0 = ex2a(s0 - m);
            float e1 = ex2a(s1 - m);
            float e2 = ex2a(s2 - m);
            float e3 = ex2a(s3 - m);
            float sum = (e0 + e1) + (e2 + e3);
            float e_a = h ? e2 : e0;
            float e_b = h ? e3 : e1;
            int   p_a = h ? pv.z : pv.x;
            int   p_b = h ? pv.w : pv.y;
            float za_h = (g < D) ? (e_a * z_sh[p_a * DP + g]
                                  + e_b * z_sh[p_b * DP + g]) : 0.f;
            float za = za_h + __shfl_xor_sync(0xffffffffu, za_h, 1);
            outv = (g < D) ? fmaxf(mp + __fdividef(za, sum), 0.f) : 0.f;
        } else if (h == 0 && g < D) {
            // rare (t=0 always; t>0 with p~0.0016): relu(W_single@atom + b)
            const float* arow = atoms + (d * NNODE + t) * D;   // bcast, L2-hot
            const float* wrow = W_single + g * D;
            float acc = b_single[g];
#pragma unroll
            for (int k = 0; k < 31; k++) {
                float2 av = *(const float2*)(arow + 2 * k);
                float2 wv = *(const float2*)(wrow + 2 * k);
                acc += wv.x * av.x + wv.y * av.y;
            }
            outv = fmaxf(acc, 0.f);
        }
        if (h == 0) out_sh[my_oidx] = (g < D) ? outv : 0.f;   // interleaved
        __syncthreads();

        {   // half-dot via interleaved reads: lanes' pair hits ONE 128B line
            ull a0 = 0ULL, a1 = 0ULL, a2v = 0ULL, a3 = 0ULL;
            const char* ob = (const char*)out_sh + h * 16;
#pragma unroll
            for (int jj = 0; jj < 8; jj += 2) {
                ulonglong2 oa = *(const ulonglong2*)(ob + 32 * jj);
                ulonglong2 oc = *(const ulonglong2*)(ob + 32 * (jj + 1));
                ffma2(a0,  Wr2[2 * jj],     oa.x);
                ffma2(a1,  Wr2[2 * jj + 1], oa.y);
                ffma2(a2v, Wr2[2 * jj + 2], oc.x);
                ffma2(a3,  Wr2[2 * jj + 3], oc.y);
            }
            float2 f0 = unpack2(a0), f1 = unpack2(a1);
            float2 f2 = unpack2(a2v), f3 = unpack2(a3);
            float part = ((f0.x + f0.y) + (f1.x + f1.y))
                       + ((f2.x + f2.y) + (f3.x + f3.y));
            float tot = part + __shfl_xor_sync(0xffffffffu, part, 1);
            if (h == 0) {
                if (g < D)       z_sh[t * DP + g] = tot;
                else if (g == D) sdot_sh[t] = tot * LOG2E;   // pre-scaled
            }
        }
        if (t == NNODE - 1 && h == 0 && g < D) g_last[d * D + g] = outv;
        __syncthreads();
    }

    // fused logit: L[d] = out_47 . dag_w  (out_sh interleaved)
    float lg = (tid < D) ? out_sh[oidx(tid)] * dagw_t : 0.f;
#pragma unroll
    for (int o = 16; o > 0; o >>= 1) lg += __shfl_xor_sync(0xffffffffu, lg, o);
    if ((tid & 31) == 0) red_sh[tid >> 5] = lg;
    __syncthreads();
    if (tid == 0) {
        float L = (red_sh[0] + red_sh[1]) + (red_sh[2] + red_sh[3]);
        g_logit[d] = L;
        atomicMax(&g_maxbits, enc_f(L));
    }
}

// ============================================================================
// K3: partial softmax-pool. 256 blocks x 64 threads, 64 DAGs per block.
// ============================================================================
__global__ void __launch_bounds__(64) k_pool() {
    __shared__ float e_sh[64];
    int tid = threadIdx.x;
    long base = (long)blockIdx.x * 64;
    int mb = g_maxbits;
    float M = __int_as_float(mb >= 0 ? mb : (mb ^ 0x7FFFFFFF));
    e_sh[tid] = __expf(g_logit[base + tid] - M);
    __syncthreads();
    if (tid < D) {
        float pool = 0.f;
#pragma unroll 4
        for (int i = 0; i < 64; i++)
            pool += e_sh[i] * g_last[(base + i) * D + tid];
        g_part[blockIdx.x * 64 + tid] = pool;
    } else if (tid == D) {
        float sE = 0.f;
#pragma unroll
        for (int i = 0; i < 64; i++) sE += e_sh[i];
        g_part[blockIdx.x * 64 + D] = sE;
    }
}

// ============================================================================
// K4: reduce partials -> pooled; out = sigmoid(W_final @ pooled + b_final)
// ============================================================================
__global__ void __launch_bounds__(512) k_final(const float* __restrict__ W_final,
                                               const float* __restrict__ b_final,
                                               float* __restrict__ out) {
    __shared__ float part[8][64];
    __shared__ float pooled[64];
    int tid = threadIdx.x;
    int c = tid >> 6, col = tid & 63;
    float s = 0.f;
    for (int b = c; b < NPOOL; b += 8) s += g_part[b * 64 + col];
    part[c][col] = s;
    __syncthreads();
    if (tid < 64) {
        float t = 0.f;
#pragma unroll
        for (int i = 0; i < 8; i++) t += part[i][tid];
        pooled[tid] = t;            // pooled[62] = sumE
    }
    __syncthreads();
    float inv = 1.f / pooled[D];
    if (tid < NCLS) {
        float acc = 0.f;
#pragma unroll
        for (int k = 0; k < D; k++) acc += W_final[tid * D + k] * pooled[k];
        acc = b_final[tid] + acc * inv;
        out[tid] = 1.f / (1.f + expf(-acc));
    }
}

// ============================================================================
extern "C" void kernel_launch(void* const* d_in, const int* in_sizes, int n_in,
                              void* d_out, int out_size) {
    const float* atoms    = (const float*)d_in[0];
    const int*   preds    = (const int*)  d_in[1];
    const float* W_single = (const float*)d_in[2];
    const float* b_single = (const float*)d_in[3];
    const float* W_merge  = (const float*)d_in[4];
    const float* b_merge  = (const float*)d_in[5];
    const float* att_w    = (const float*)d_in[6];
    const float* dag_w    = (const float*)d_in[7];
    const float* W_final  = (const float*)d_in[8];
    const float* b_final  = (const float*)d_in[9];
    float* out = (float*)d_out;

    // capture slot = 4th launch -> k_atomP (verify this round's fix)
    k_nop<<<1, 32>>>();
    k_reset<<<1, 32>>>();
    k_nop<<<1, 32>>>();
    k_atomP<<<NDAG * NNODE / 128, 256>>>(atoms, W_merge, b_merge);
    k_scan<<<NDAG, 128>>>(atoms, preds, W_single, b_single, W_merge, att_w, dag_w);
    k_pool<<<NPOOL, 64>>>();
    k_final<<<1, 512>>>(W_final, b_final, out);
}